// round 17
// baseline (speedup 1.0000x reference)
#include <cuda_runtime.h>
#include <cuda_fp16.h>
#include <cstdint>
#include <math.h>

// LayerNorm(768) -> Linear(768->64) -> SiLU -> unpatchify, fused.
// LN folded into epilogue: y = rstd*(x@W'^T - mu*S) + b', W' = W*ln_w (fp16).
// fp16 mma.sync.m16n8k16 with W as A-operand (m=64, 4 m-tiles) and x as
// B-operand (n=8 rows). Warp-autonomous, per-warp work stealing over 8-row
// units. x streamed via per-warp 2-stage cp.async ring with 512B row-granules
// (halved DRAM row activations). W' in smem (96KB); 512 threads, 1 CTA/SM.

#define KDIM 768
#define ODIM 64
#define NUNITS 16384           // 131072 rows / 8
#define NSTAGES 6              // K stages of 128 floats (512B per row)

#define W_SMEM_B  98304
#define WP_RING_B 8192         // 2 stages x 4KB
#define SMEM_DYN  (W_SMEM_B + 16 * WP_RING_B)   // 229376 B

__device__ __align__(16) __half d_Wh[48 * 4 * 32 * 8];  // [kstep][mt][lane][frag halves]
__device__ float d_S[ODIM];
__device__ float d_bp[ODIM];
__device__ unsigned d_ctr;

static __device__ __forceinline__ uint32_t s2u(const void* p) {
    uint32_t a;
    asm("{ .reg .u64 t; cvta.to.shared.u64 t, %1; cvt.u32.u64 %0, t; }" : "=r"(a) : "l"(p));
    return a;
}
static __device__ __forceinline__ uint32_t pack2(float lo, float hi) {
    uint32_t r;
    asm("cvt.rn.f16x2.f32 %0, %1, %2;" : "=r"(r) : "f"(hi), "f"(lo));
    return r;
}
static __device__ __forceinline__ void mma_f16(float* d,
    uint32_t a0, uint32_t a1, uint32_t a2, uint32_t a3,
    uint32_t b0, uint32_t b1)
{
    asm volatile(
        "mma.sync.aligned.m16n8k16.row.col.f32.f16.f16.f32 "
        "{%0,%1,%2,%3}, {%4,%5,%6,%7}, {%8,%9}, {%0,%1,%2,%3};"
        : "+f"(d[0]), "+f"(d[1]), "+f"(d[2]), "+f"(d[3])
        : "r"(a0), "r"(a1), "r"(a2), "r"(a3), "r"(b0), "r"(b1));
}
static __device__ __forceinline__ void cp16(uint32_t dst, const void* src) {
    asm volatile("cp.async.cg.shared.global [%0], [%1], 16;"
                 :: "r"(dst), "l"(src) : "memory");
}
static __device__ __forceinline__ void cp_commit() {
    asm volatile("cp.async.commit_group;" ::: "memory");
}
static __device__ __forceinline__ void cp_wait2() {
    asm volatile("cp.async.wait_group 2;" ::: "memory");
}

// ---------------- merged prep kernel ----------------
// A-frag layout for W': uint4 per (kstep, mt, lane): halves
//   [a0.lo a0.hi a1.lo a1.hi a2.lo a2.hi a3.lo a3.hi]
//   a0=W[mt*16+u][2q,2q+1] a1=W[..+u+8][2q..] a2=W[u][2q+8..] a3=W[u+8][2q+8..]
__global__ void prep(const float* __restrict__ W, const float* __restrict__ lnw,
                     const float* __restrict__ lnb, const float* __restrict__ b,
                     unsigned ctr_init)
{
    __shared__ float red[2][8];
    const int bid = blockIdx.x, t = threadIdx.x;
    const int idx = bid * 256 + t;
    if (idx == 0) d_ctr = ctr_init;

    if (idx < ODIM * KDIM) {
        int o = idx / KDIM, k = idx - o * KDIM;
        int mt = o >> 4, u = o & 7, hi = (o >> 3) & 1;
        int kstep = k >> 4, kl = k & 15;
        int q = (kl & 7) >> 1, halfk = kl & 1;
        int reg = hi + ((kl >= 8) ? 2 : 0);
        d_Wh[(size_t)(kstep * 128 + mt * 32 + u * 4 + q) * 8 + reg * 2 + halfk] =
            __float2half_rn(W[idx] * lnw[k]);
    }

    if (bid < ODIM) {
        const int o = bid;
        float s = 0.f, bs = 0.f;
        for (int k = t; k < KDIM; k += 256) {
            float w = W[o * KDIM + k];
            s  += __half2float(__float2half_rn(w * lnw[k]));
            bs += lnb[k] * w;
        }
        #pragma unroll
        for (int d = 16; d; d >>= 1) {
            s  += __shfl_xor_sync(0xffffffffu, s, d);
            bs += __shfl_xor_sync(0xffffffffu, bs, d);
        }
        if ((t & 31) == 0) { red[0][t >> 5] = s; red[1][t >> 5] = bs; }
        __syncthreads();
        if (t == 0) {
            float S = 0.f, B = 0.f;
            #pragma unroll
            for (int i = 0; i < 8; i++) { S += red[0][i]; B += red[1][i]; }
            d_S[o] = S;
            d_bp[o] = b[o] + B;
        }
    }
}

// ---------------- main kernel ----------------
extern __shared__ char smc[];

__global__ void __launch_bounds__(512, 1)
ln_gemm_silu(const float* __restrict__ x, float* __restrict__ out)
{
    __shared__ float sS[64], sbp[64];

    const int tid  = threadIdx.x;
    const int lane = tid & 31;
    const int warp = tid >> 5;

    // one-time: copy W' into smem; load S/bp
    {
        const uint4* wsrc = (const uint4*)d_Wh;
        uint4* wdst = (uint4*)smc;
        for (int i = tid; i < W_SMEM_B / 16; i += 512) wdst[i] = wsrc[i];
        if (tid < ODIM) { sS[tid] = d_S[tid]; sbp[tid] = d_bp[tid]; }
    }
    __syncthreads();

    const int u = lane >> 2;       // consumer: x-row u; W rows u, u+8 per m-tile
    const int q = lane & 3;
    const int r0 = lane >> 3;      // producer: rows r0, r0+4
    const int cc = lane & 7;       // 16B chunk within 128B

    char* ring = smc + W_SMEM_B + warp * WP_RING_B;
    const uint32_t ring_u = s2u(ring);

    // producer swizzled dst offsets (row*512 + (cc^row)*16); chunk j adds j*128
    uint32_t pdst[2];
    pdst[0] = (uint32_t)(r0 * 512 + ((cc ^ r0) << 4));
    pdst[1] = (uint32_t)((r0 + 4) * 512 + ((cc ^ (r0 + 4)) << 4));

    unsigned unit = blockIdx.x * 16 + warp;
    while (unit < NUNITS) {
        float acc[4][4];
        #pragma unroll
        for (int mt = 0; mt < 4; mt++)
            #pragma unroll
            for (int c = 0; c < 4; c++) acc[mt][c] = 0.f;

        float st0 = 0.f, st1 = 0.f;

        const char* gxl = (const char*)x + (size_t)(unit * 8 + r0) * 3072 + cc * 16;

        // ---- prologue: stage 0 groups A, B ----
        #pragma unroll
        for (int g = 0; g < 2; g++) {
            const char* gs = gxl;
            #pragma unroll
            for (int j2 = 0; j2 < 2; j2++) {
                int j = g * 2 + j2;
                cp16(ring_u + pdst[0] + j * 128, gs + j * 128);
                cp16(ring_u + pdst[1] + j * 128, gs + 12288 + j * 128);
            }
            cp_commit();
        }

        #pragma unroll 2
        for (int s = 0; s < NSTAGES; s++) {
            const char* sbc = ring + (s & 1) * 4096;

            #pragma unroll
            for (int h = 0; h < 2; h++) {
                // issue next stage's group h; commit unconditionally
                if (s + 1 < NSTAGES) {
                    uint32_t db = ring_u + ((s + 1) & 1) * 4096;
                    const char* gs = gxl + (s + 1) * 512;
                    #pragma unroll
                    for (int j2 = 0; j2 < 2; j2++) {
                        int j = h * 2 + j2;
                        cp16(db + pdst[0] + j * 128, gs + j * 128);
                        cp16(db + pdst[1] + j * 128, gs + 12288 + j * 128);
                    }
                }
                cp_commit();
                cp_wait2();

                // consume k-steps h*4 .. h*4+3 of this stage
                #pragma unroll
                for (int kk = 0; kk < 4; kk++) {
                    const int kg = h * 4 + kk;                // 0..7 within stage
                    const int c0 = (kg * 4 + (q >> 1)) ^ u;
                    const int c1 = (kg * 4 + 2 + (q >> 1)) ^ u;
                    float2 v0 = *(const float2*)(sbc + u * 512 + c0 * 16 + (q & 1) * 8);
                    float2 v1 = *(const float2*)(sbc + u * 512 + c1 * 16 + (q & 1) * 8);
                    st0 += v0.x + v0.y + v1.x + v1.y;
                    st1 += v0.x*v0.x + v0.y*v0.y + v1.x*v1.x + v1.y*v1.y;
                    uint32_t b0 = pack2(v0.x, v0.y);          // x[u][2q], [2q+1]
                    uint32_t b1 = pack2(v1.x, v1.y);          // x[u][2q+8], [2q+9]

                    const char* wp = smc + (size_t)((s * 8 + kg) * 128 + lane) * 16;
                    #pragma unroll
                    for (int mt = 0; mt < 4; mt++) {
                        uint4 av = *(const uint4*)(wp + mt * 512);
                        mma_f16(acc[mt], av.x, av.y, av.z, av.w, b0, b1);
                    }
                }
            }
        }

        // ---- row stats (row u) reduced over the 4 q-lanes ----
        st0 += __shfl_xor_sync(0xffffffffu, st0, 1);
        st1 += __shfl_xor_sync(0xffffffffu, st1, 1);
        st0 += __shfl_xor_sync(0xffffffffu, st0, 2);
        st1 += __shfl_xor_sync(0xffffffffu, st1, 2);
        float mu = st0 * (1.f / 768.f);
        float rs = rsqrtf(st1 * (1.f / 768.f) - mu * mu + 1e-5f);

        // redistribute: this lane needs rows 2q, 2q+1 (its D-frag columns)
        float muE[2], rsE[2];
        muE[0] = __shfl_sync(0xffffffffu, mu, (q << 3) | q);
        rsE[0] = __shfl_sync(0xffffffffu, rs, (q << 3) | q);
        muE[1] = __shfl_sync(0xffffffffu, mu, ((q << 3) + 4) | q);
        rsE[1] = __shfl_sync(0xffffffffu, rs, ((q << 3) + 4) | q);

        // ---- epilogue: LN-correct, bias, SiLU, unpatchify ----
        {
            float* outb = out + ((size_t)(unit >> 3) << 12);
            const int rrb = (unit & 7) << 2;
            #pragma unroll
            for (int e = 0; e < 2; e++) {
                const int row = 2 * q + e;
                const int cl  = row * 4 + (u & 3);
                #pragma unroll
                for (int mt = 0; mt < 4; mt++) {
                    #pragma unroll
                    for (int hi = 0; hi < 2; hi++) {
                        const int o = mt * 16 + u + hi * 8;
                        float g = acc[mt][hi * 2 + e];
                        float y = rsE[e] * (g - muE[e] * sS[o]) + sbp[o];
                        float sv = y / (1.f + __expf(-y));
                        const int rr = rrb + (u >> 2) + hi * 2;
                        outb[((mt * 32 + rr) << 5) + cl] = sv;
                    }
                }
            }
        }

        // ---- per-warp work steal ----
        unsigned nx = 0;
        if (lane == 0) nx = atomicAdd(&d_ctr, 1u);
        unit = __shfl_sync(0xffffffffu, nx, 0);
    }
}

extern "C" void kernel_launch(void* const* d_in, const int* in_sizes, int n_in,
                              void* d_out, int out_size)
{
    const float* x   = (const float*)d_in[0];
    const float* lnw = (const float*)d_in[1];
    const float* lnb = (const float*)d_in[2];
    const float* W   = (const float*)d_in[3];
    const float* b   = (const float*)d_in[4];
    float* out = (float*)d_out;

    cudaFuncSetAttribute(ln_gemm_silu,
                         cudaFuncAttributeMaxDynamicSharedMemorySize, SMEM_DYN);

    int dev = 0, sms = 148;
    cudaGetDevice(&dev);
    cudaDeviceGetAttribute(&sms, cudaDevAttrMultiProcessorCount, dev);
    unsigned grid = (unsigned)sms;

    prep<<<(ODIM * KDIM + 255) / 256, 256>>>(W, lnw, lnb, b, grid * 16u);
    ln_gemm_silu<<<grid, 512, SMEM_DYN>>>(x, out);
}